// round 10
// baseline (speedup 1.0000x reference)
#include <cuda_runtime.h>
#include <cuda_bf16.h>
#include <cstdint>
#include <math_constants.h>

// Problem shape (fixed per reference)
#define B_  32
#define S_  4096
#define H_  1024
#define CHUNKS 16             // s-chunks per batch (best measured config)
#define SC  (S_ / CHUNKS)     // 256 rows per chunk
#define TR  8                 // rows per tile (one row per consumer warp)
#define NT  (SC / TR)         // 32 tiles per chunk
#define NS  3                 // pipeline stages
#define TILE_BYTES (TR * H_ * 4)       // 32 KB
#define STAGE_FLOATS (TR * H_)
#define NTHREADS 288          // 8 consumer warps + 1 producer warp

// SMEM layout (bytes)
#define SM_STAGES_OFF 0
#define SM_DEC_OFF    (NS * TILE_BYTES)              // 98304
#define SM_ML_OFF     (SM_DEC_OFF + H_ * 4)          // m[8], l[8]
#define SM_FLAG_OFF   (SM_ML_OFF + 64)               // int flag
#define SM_FULL_OFF   (SM_FLAG_OFF + 8)              // NS full mbars
#define SM_EMPTY_OFF  (SM_FULL_OFF + NS * 8)         // NS empty mbars
#define SMEM_BYTES    (SM_EMPTY_OFF + NS * 8 + 8)

// Scratch (__device__ globals: allocation-free)
__device__ float g_m[B_ * CHUNKS];
__device__ float g_l[B_ * CHUNKS];
__device__ float g_ctx[(size_t)B_ * CHUNKS * H_];
__device__ int   g_cnt[B_];   // zero-init; reset in-kernel each launch

__device__ __forceinline__ uint32_t smem_u32(const void* p) {
    uint32_t a;
    asm("{ .reg .u64 t; cvta.to.shared.u64 t, %1; cvt.u32.u64 %0, t; }"
        : "=r"(a) : "l"(p));
    return a;
}
__device__ __forceinline__ void mbar_init(uint32_t mbar, uint32_t cnt) {
    asm volatile("mbarrier.init.shared.b64 [%0], %1;" :: "r"(mbar), "r"(cnt) : "memory");
}
__device__ __forceinline__ void mbar_arrive(uint32_t mbar) {
    asm volatile("mbarrier.arrive.release.cta.shared::cta.b64 _, [%0];"
                 :: "r"(mbar) : "memory");
}
__device__ __forceinline__ void mbar_expect_tx(uint32_t mbar, uint32_t bytes) {
    asm volatile("mbarrier.arrive.expect_tx.shared.b64 _, [%0], %1;"
                 :: "r"(mbar), "r"(bytes) : "memory");
}
__device__ __forceinline__ void mbar_wait(uint32_t mbar, uint32_t parity) {
    uint32_t done;
    asm volatile(
        "{\n\t"
        ".reg .pred p;\n\t"
        "mbarrier.try_wait.parity.acquire.cta.shared::cta.b64 p, [%1], %2;\n\t"
        "selp.b32 %0, 1, 0, p;\n\t"
        "}" : "=r"(done) : "r"(mbar), "r"(parity) : "memory");
    if (!done) {
        asm volatile(
            "{\n\t"
            ".reg .pred P1;\n\t"
            "WAIT_LOOP_%=:\n\t"
            "mbarrier.try_wait.parity.acquire.cta.shared::cta.b64 P1, [%0], %1, 0x989680;\n\t"
            "@P1 bra.uni WAIT_DONE_%=;\n\t"
            "bra.uni WAIT_LOOP_%=;\n\t"
            "WAIT_DONE_%=:\n\t"
            "}" :: "r"(mbar), "r"(parity) : "memory");
    }
}
__device__ __forceinline__ void bulk_g2s(uint32_t dst, const void* src,
                                         uint32_t bytes, uint32_t mbar) {
    asm volatile(
        "cp.async.bulk.shared::cluster.global.mbarrier::complete_tx::bytes "
        "[%0], [%1], %2, [%3];"
        :: "r"(dst), "l"(src), "r"(bytes), "r"(mbar) : "memory");
}

// ---------------------------------------------------------------------------
// Warp-specialized fused kernel:
//   warps 0-7: barrier-free consumers (per-warp online softmax)
//   warp 8:    TMA producer (waits per-stage empty mbarriers)
//   last CTA per batch: combine (threadfence-reduction)
// ---------------------------------------------------------------------------
__global__ void __launch_bounds__(NTHREADS, 2)
attn_fused(const float* __restrict__ dec,
           const float* __restrict__ enc,
           float* __restrict__ ctx_out,       // d_out
           float* __restrict__ attn_out)      // d_out + B_*H_
{
    extern __shared__ __align__(16) char smem[];
    float* s_stage = (float*)(smem + SM_STAGES_OFF);
    float* s_dec   = (float*)(smem + SM_DEC_OFF);
    float* s_m     = (float*)(smem + SM_ML_OFF);
    float* s_l     = s_m + TR;
    int*   s_last  = (int*)(smem + SM_FLAG_OFF);
    uint32_t smbase = smem_u32(smem);
    uint32_t full0  = smbase + SM_FULL_OFF;
    uint32_t empty0 = smbase + SM_EMPTY_OFF;

    const int b     = blockIdx.y;
    const int chunk = blockIdx.x;
    const int tid   = threadIdx.x;
    const int w     = tid >> 5;
    const int lid   = tid & 31;

    const float* encB = enc + ((size_t)b * S_ + (size_t)chunk * SC) * H_;

    if (tid == 0) {
        #pragma unroll
        for (int s = 0; s < NS; s++) {
            mbar_init(full0  + 8u * s, 1);   // TMA expect_tx
            mbar_init(empty0 + 8u * s, TR);  // one arrive per consumer warp
        }
    }
    if (tid < 256)
        ((float4*)s_dec)[tid] = ((const float4*)(dec + (size_t)b * H_))[tid];
    __syncthreads();

    if (w == 8) {
        // ---------------- producer warp ----------------
        if (lid == 0) {
            #pragma unroll
            for (int s = 0; s < NS; s++) {
                mbar_expect_tx(full0 + 8u * s, TILE_BYTES);
                bulk_g2s(smbase + SM_STAGES_OFF + s * TILE_BYTES,
                         encB + (size_t)s * TR * H_, TILE_BYTES, full0 + 8u * s);
            }
            for (int t = NS; t < NT; t++) {
                const int st = t % NS;
                const uint32_t eph = (uint32_t)(((t - NS) / NS) & 1);
                mbar_wait(empty0 + 8u * st, eph);
                mbar_expect_tx(full0 + 8u * st, TILE_BYTES);
                bulk_g2s(smbase + SM_STAGES_OFF + st * TILE_BYTES,
                         encB + (size_t)t * TR * H_, TILE_BYTES, full0 + 8u * st);
            }
        }
    } else {
        // ---------------- consumer warps (barrier-free loop) --------------
        float4 dreg[8];
        #pragma unroll
        for (int k = 0; k < 8; k++) dreg[k] = ((float4*)s_dec)[k * 32 + lid];

        float4 acc[8];
        #pragma unroll
        for (int k = 0; k < 8; k++) acc[k] = make_float4(0.f, 0.f, 0.f, 0.f);
        float m = -CUDART_INF_F;
        float l = 0.f;

        for (int t = 0; t < NT; t++) {
            const int st = t % NS;
            const uint32_t ph = (uint32_t)((t / NS) & 1);
            mbar_wait(full0 + 8u * st, ph);

            // warp w's row into registers (single SMEM read of this row)
            float4* er = (float4*)(s_stage + st * STAGE_FLOATS) + w * 256;
            float4 v[8];
            #pragma unroll
            for (int k = 0; k < 8; k++) v[k] = er[k * 32 + lid];

            // this warp is done with the stage -> let producer refill
            if (lid == 0) mbar_arrive(empty0 + 8u * st);

            float p = 0.f;
            #pragma unroll
            for (int k = 0; k < 8; k++) {
                p = fmaf(dreg[k].x, v[k].x, p);
                p = fmaf(dreg[k].y, v[k].y, p);
                p = fmaf(dreg[k].z, v[k].z, p);
                p = fmaf(dreg[k].w, v[k].w, p);
            }
            #pragma unroll
            for (int off = 16; off > 0; off >>= 1)
                p += __shfl_xor_sync(0xFFFFFFFFu, p, off);

            if (lid == 0)
                attn_out[(size_t)b * S_ + chunk * SC + t * TR + w] = p;  // raw

            if (p > m) {
                float scale = __expf(m - p);
                m = p;
                l *= scale;
                #pragma unroll
                for (int k = 0; k < 8; k++) {
                    acc[k].x *= scale; acc[k].y *= scale;
                    acc[k].z *= scale; acc[k].w *= scale;
                }
            }
            float wgt = __expf(p - m);
            l += wgt;
            #pragma unroll
            for (int k = 0; k < 8; k++) {
                acc[k].x = fmaf(wgt, v[k].x, acc[k].x);
                acc[k].y = fmaf(wgt, v[k].y, acc[k].y);
                acc[k].z = fmaf(wgt, v[k].z, acc[k].z);
                acc[k].w = fmaf(wgt, v[k].w, acc[k].w);
            }
        }

        if (lid == 0) { s_m[w] = m; s_l[w] = l; }

        // stash scaled acc after the chunk-wide (M,L) is known (below)
        // -- need barrier first; do it after joint __syncthreads.
        // Temporarily keep acc in registers; merge below.
        __syncthreads();   // joins producer too

        float Mc = -CUDART_INF_F;
        #pragma unroll
        for (int r = 0; r < TR; r++) Mc = fmaxf(Mc, s_m[r]);
        float Lc = 0.f;
        #pragma unroll
        for (int r = 0; r < TR; r++) Lc += s_l[r] * __expf(s_m[r] - Mc);
        float myscale = __expf(m - Mc);   // uniform within warp

        float4* dst = (float4*)s_stage + w * 256;
        #pragma unroll
        for (int k = 0; k < 8; k++) {
            float4 a = acc[k];
            a.x *= myscale; a.y *= myscale; a.z *= myscale; a.w *= myscale;
            dst[k * 32 + lid] = a;
        }
        __syncthreads();

        float4* sb = (float4*)s_stage;
        float4 s = make_float4(0.f, 0.f, 0.f, 0.f);
        #pragma unroll
        for (int r = 0; r < TR; r++) {
            float4 x = sb[r * 256 + tid];
            s.x += x.x; s.y += x.y; s.z += x.z; s.w += x.w;
        }
        const int cid = b * CHUNKS + chunk;
        ((float4*)(g_ctx + (size_t)cid * H_))[tid] = s;
        if (tid == 0) { g_m[cid] = Mc; g_l[cid] = Lc; }
    }

    // producer warp joins the two epilogue barriers
    if (w == 8) { __syncthreads(); __syncthreads(); }

    // ---- last CTA of this batch performs the combine ----
    __threadfence();   // release partials + raw scores
    if (tid == 0) {
        int old = atomicAdd(&g_cnt[b], 1);
        *s_last = (old == CHUNKS - 1);
    }
    __syncthreads();
    if (!*s_last) return;

    __threadfence();   // acquire all CTAs' partials/scores
    if (tid == 0) g_cnt[b] = 0;   // reset for next graph replay

    float M = -CUDART_INF_F;
    #pragma unroll
    for (int c = 0; c < CHUNKS; c++) M = fmaxf(M, g_m[b * CHUNKS + c]);
    float L = 0.f;
    #pragma unroll
    for (int c = 0; c < CHUNKS; c++)
        L += g_l[b * CHUNKS + c] * __expf(g_m[b * CHUNKS + c] - M);
    const float invL = 1.0f / L;

    if (tid < 256) {
        // context: 1024 floats = 256 float4, one per thread
        float4 cs = make_float4(0.f, 0.f, 0.f, 0.f);
        #pragma unroll
        for (int c = 0; c < CHUNKS; c++) {
            float ef = __expf(g_m[b * CHUNKS + c] - M);
            float4 v = ((const float4*)(g_ctx + (size_t)(b * CHUNKS + c) * H_))[tid];
            cs.x = fmaf(ef, v.x, cs.x);
            cs.y = fmaf(ef, v.y, cs.y);
            cs.z = fmaf(ef, v.z, cs.z);
            cs.w = fmaf(ef, v.w, cs.w);
        }
        cs.x *= invL; cs.y *= invL; cs.z *= invL; cs.w *= invL;
        ((float4*)(ctx_out + (size_t)b * H_))[tid] = cs;

        // attn: normalize this batch's 4096 raw scores (1024 float4)
        float4* a4 = (float4*)(attn_out + (size_t)b * S_);
        #pragma unroll
        for (int i = 0; i < 4; i++) {
            float4 x = a4[i * 256 + tid];
            x.x = __expf(x.x - M) * invL;
            x.y = __expf(x.y - M) * invL;
            x.z = __expf(x.z - M) * invL;
            x.w = __expf(x.w - M) * invL;
            a4[i * 256 + tid] = x;
        }
    }
}

extern "C" void kernel_launch(void* const* d_in, const int* in_sizes, int n_in,
                              void* d_out, int out_size) {
    const float* dec = (const float*)d_in[0];   // (32, 1024)
    const float* enc = (const float*)d_in[1];   // (32, 4096, 1024)
    float* out = (float*)d_out;                 // [context (32*1024) | attn (32*4096)]
    float* ctx_out  = out;
    float* attn_out = out + (size_t)B_ * H_;

    cudaFuncSetAttribute(attn_fused, cudaFuncAttributeMaxDynamicSharedMemorySize,
                         SMEM_BYTES);

    dim3 grid(CHUNKS, B_);
    attn_fused<<<grid, NTHREADS, SMEM_BYTES>>>(dec, enc, ctx_out, attn_out);
}

// round 12
// speedup vs baseline: 1.0394x; 1.0394x over previous
#include <cuda_runtime.h>
#include <cuda_bf16.h>
#include <cstdint>
#include <math_constants.h>

// Problem shape (fixed per reference)
#define B_  32
#define S_  4096
#define H_  1024
#define CHUNKS 16             // s-chunks per batch (best measured config)
#define SC  (S_ / CHUNKS)     // 256 rows per chunk
#define TR  8                 // rows per tile (one row per warp)
#define NT  (SC / TR)         // 32 tiles per chunk
#define NS  3                 // pipeline stages
#define TILE_BYTES (TR * H_ * 4)       // 32 KB
#define STAGE_FLOATS (TR * H_)

// SMEM layout (bytes)
#define SM_STAGES_OFF 0
#define SM_DEC_OFF    (NS * TILE_BYTES)              // 98304
#define SM_ML_OFF     (SM_DEC_OFF + H_ * 4)          // m[8], l[8]
#define SM_FLAG_OFF   (SM_ML_OFF + 64)               // int flag
#define SM_MBAR_OFF   (SM_FLAG_OFF + 8)
#define SMEM_BYTES    (SM_MBAR_OFF + NS * 8 + 8)

// Scratch (__device__ globals: allocation-free)
__device__ float g_m[B_ * CHUNKS];
__device__ float g_l[B_ * CHUNKS];
__device__ float g_ctx[(size_t)B_ * CHUNKS * H_];
__device__ int   g_cnt[B_];   // zero-initialized; reset in-kernel each launch

__device__ __forceinline__ uint32_t smem_u32(const void* p) {
    uint32_t a;
    asm("{ .reg .u64 t; cvta.to.shared.u64 t, %1; cvt.u32.u64 %0, t; }"
        : "=r"(a) : "l"(p));
    return a;
}

__device__ __forceinline__ void mbar_init(uint32_t mbar, uint32_t cnt) {
    asm volatile("mbarrier.init.shared.b64 [%0], %1;" :: "r"(mbar), "r"(cnt) : "memory");
}
__device__ __forceinline__ void mbar_expect_tx(uint32_t mbar, uint32_t bytes) {
    asm volatile("mbarrier.arrive.expect_tx.shared.b64 _, [%0], %1;"
                 :: "r"(mbar), "r"(bytes) : "memory");
}
__device__ __forceinline__ void mbar_wait(uint32_t mbar, uint32_t parity) {
    uint32_t done;
    asm volatile(
        "{\n\t"
        ".reg .pred p;\n\t"
        "mbarrier.try_wait.parity.acquire.cta.shared::cta.b64 p, [%1], %2;\n\t"
        "selp.b32 %0, 1, 0, p;\n\t"
        "}" : "=r"(done) : "r"(mbar), "r"(parity) : "memory");
    if (!done) {
        asm volatile(
            "{\n\t"
            ".reg .pred P1;\n\t"
            "WAIT_LOOP_%=:\n\t"
            "mbarrier.try_wait.parity.acquire.cta.shared::cta.b64 P1, [%0], %1, 0x989680;\n\t"
            "@P1 bra.uni WAIT_DONE_%=;\n\t"
            "bra.uni WAIT_LOOP_%=;\n\t"
            "WAIT_DONE_%=:\n\t"
            "}" :: "r"(mbar), "r"(parity) : "memory");
    }
}
__device__ __forceinline__ void bulk_g2s(uint32_t dst, const void* src,
                                         uint32_t bytes, uint32_t mbar) {
    asm volatile(
        "cp.async.bulk.shared::cluster.global.mbarrier::complete_tx::bytes "
        "[%0], [%1], %2, [%3];"
        :: "r"(dst), "l"(src), "r"(bytes), "r"(mbar) : "memory");
}

// ---------------------------------------------------------------------------
// Single fused kernel: streaming online-softmax pass + last-CTA-per-batch
// combine (threadfence-reduction pattern).
// Early-release variant: __syncthreads moved to right after the register
// loads so the TMA refill is issued ~200 cyc earlier per tile.
// ---------------------------------------------------------------------------
__global__ void __launch_bounds__(256, 2)
attn_fused(const float* __restrict__ dec,
           const float* __restrict__ enc,
           float* __restrict__ ctx_out,       // d_out
           float* __restrict__ attn_out)      // d_out + B_*H_
{
    extern __shared__ __align__(16) char smem[];
    float* s_stage = (float*)(smem + SM_STAGES_OFF);
    float* s_dec   = (float*)(smem + SM_DEC_OFF);
    float* s_m     = (float*)(smem + SM_ML_OFF);
    float* s_l     = s_m + TR;
    int*   s_last  = (int*)(smem + SM_FLAG_OFF);
    uint32_t smbase = smem_u32(smem);
    uint32_t mbar0  = smbase + SM_MBAR_OFF;

    const int b     = blockIdx.y;
    const int chunk = blockIdx.x;
    const int tid   = threadIdx.x;
    const int w     = tid >> 5;
    const int lid   = tid & 31;

    const float* encB = enc + ((size_t)b * S_ + (size_t)chunk * SC) * H_;

    if (tid == 0) {
        #pragma unroll
        for (int s = 0; s < NS; s++) mbar_init(mbar0 + 8u * s, 1);
    }
    ((float4*)s_dec)[tid] = ((const float4*)(dec + (size_t)b * H_))[tid];
    __syncthreads();

    if (tid == 0) {
        #pragma unroll
        for (int s = 0; s < NS; s++) {
            mbar_expect_tx(mbar0 + 8u * s, TILE_BYTES);
            bulk_g2s(smbase + SM_STAGES_OFF + s * TILE_BYTES,
                     encB + (size_t)s * TR * H_, TILE_BYTES, mbar0 + 8u * s);
        }
    }

    // decoder slice in registers
    float4 dreg[8];
    #pragma unroll
    for (int k = 0; k < 8; k++) dreg[k] = ((float4*)s_dec)[k * 32 + lid];

    float4 acc[8];
    #pragma unroll
    for (int k = 0; k < 8; k++) acc[k] = make_float4(0.f, 0.f, 0.f, 0.f);
    float m = -CUDART_INF_F;
    float l = 0.f;

    for (int t = 0; t < NT; t++) {
        const int st = t % NS;
        const uint32_t ph = (uint32_t)((t / NS) & 1);
        const uint32_t mbar = mbar0 + 8u * st;
        mbar_wait(mbar, ph);

        // warp w's row of this tile, into registers (single SMEM read)
        float4* er = (float4*)(s_stage + st * STAGE_FLOATS) + w * 256;
        float4 v[8];
        #pragma unroll
        for (int k = 0; k < 8; k++) v[k] = er[k * 32 + lid];

        // All shared reads of this stage are program-order before the barrier
        // -> stage reusable immediately; refill issues ~200cyc earlier than
        // if we synced after the score reduction.
        __syncthreads();
        if (tid == 0 && (t + NS) < NT) {
            mbar_expect_tx(mbar, TILE_BYTES);
            bulk_g2s(smbase + SM_STAGES_OFF + st * TILE_BYTES,
                     encB + (size_t)(t + NS) * TR * H_, TILE_BYTES, mbar);
        }

        float p = 0.f;
        #pragma unroll
        for (int k = 0; k < 8; k++) {
            p = fmaf(dreg[k].x, v[k].x, p);
            p = fmaf(dreg[k].y, v[k].y, p);
            p = fmaf(dreg[k].z, v[k].z, p);
            p = fmaf(dreg[k].w, v[k].w, p);
        }
        #pragma unroll
        for (int off = 16; off > 0; off >>= 1)
            p += __shfl_xor_sync(0xFFFFFFFFu, p, off);

        if (lid == 0)
            attn_out[(size_t)b * S_ + chunk * SC + t * TR + w] = p;   // raw score

        // per-warp online softmax update (overlaps with TMA refill)
        if (p > m) {
            float scale = __expf(m - p);
            m = p;
            l *= scale;
            #pragma unroll
            for (int k = 0; k < 8; k++) {
                acc[k].x *= scale; acc[k].y *= scale;
                acc[k].z *= scale; acc[k].w *= scale;
            }
        }
        float wgt = __expf(p - m);
        l += wgt;
        #pragma unroll
        for (int k = 0; k < 8; k++) {
            acc[k].x = fmaf(wgt, v[k].x, acc[k].x);
            acc[k].y = fmaf(wgt, v[k].y, acc[k].y);
            acc[k].z = fmaf(wgt, v[k].z, acc[k].z);
            acc[k].w = fmaf(wgt, v[k].w, acc[k].w);
        }
    }

    // ---- merge the 8 per-warp (m, l, acc) triples ----
    if (lid == 0) { s_m[w] = m; s_l[w] = l; }
    __syncthreads();

    float Mc = -CUDART_INF_F;
    #pragma unroll
    for (int r = 0; r < TR; r++) Mc = fmaxf(Mc, s_m[r]);
    float Lc = 0.f;
    #pragma unroll
    for (int r = 0; r < TR; r++) Lc += s_l[r] * __expf(s_m[r] - Mc);
    float myscale = __expf(m - Mc);   // uniform within warp

    float4* dst = (float4*)s_stage + w * 256;
    #pragma unroll
    for (int k = 0; k < 8; k++) {
        float4 a = acc[k];
        a.x *= myscale; a.y *= myscale; a.z *= myscale; a.w *= myscale;
        dst[k * 32 + lid] = a;
    }
    __syncthreads();

    float4* sb = (float4*)s_stage;
    float4 s = make_float4(0.f, 0.f, 0.f, 0.f);
    #pragma unroll
    for (int r = 0; r < TR; r++) {
        float4 x = sb[r * 256 + tid];
        s.x += x.x; s.y += x.y; s.z += x.z; s.w += x.w;
    }
    const int cid = b * CHUNKS + chunk;
    ((float4*)(g_ctx + (size_t)cid * H_))[tid] = s;
    if (tid == 0) { g_m[cid] = Mc; g_l[cid] = Lc; }

    // ---- last CTA of this batch performs the combine ----
    __threadfence();   // release partials + raw scores
    if (tid == 0) {
        int old = atomicAdd(&g_cnt[b], 1);
        *s_last = (old == CHUNKS - 1);
    }
    __syncthreads();
    if (!*s_last) return;

    __threadfence();   // acquire all CTAs' partials/scores
    if (tid == 0) g_cnt[b] = 0;   // reset for next graph replay

    float M = -CUDART_INF_F;
    #pragma unroll
    for (int c = 0; c < CHUNKS; c++) M = fmaxf(M, g_m[b * CHUNKS + c]);
    float L = 0.f;
    #pragma unroll
    for (int c = 0; c < CHUNKS; c++)
        L += g_l[b * CHUNKS + c] * __expf(g_m[b * CHUNKS + c] - M);
    const float invL = 1.0f / L;

    // context: 1024 floats = 256 float4, one per thread
    float4 cs = make_float4(0.f, 0.f, 0.f, 0.f);
    #pragma unroll
    for (int c = 0; c < CHUNKS; c++) {
        float ef = __expf(g_m[b * CHUNKS + c] - M);
        float4 v = ((const float4*)(g_ctx + (size_t)(b * CHUNKS + c) * H_))[tid];
        cs.x = fmaf(ef, v.x, cs.x);
        cs.y = fmaf(ef, v.y, cs.y);
        cs.z = fmaf(ef, v.z, cs.z);
        cs.w = fmaf(ef, v.w, cs.w);
    }
    cs.x *= invL; cs.y *= invL; cs.z *= invL; cs.w *= invL;
    ((float4*)(ctx_out + (size_t)b * H_))[tid] = cs;

    // attn: normalize this batch's 4096 raw scores (1024 float4, 4/thread)
    float4* a4 = (float4*)(attn_out + (size_t)b * S_);
    #pragma unroll
    for (int i = 0; i < 4; i++) {
        float4 x = a4[i * 256 + tid];
        x.x = __expf(x.x - M) * invL;
        x.y = __expf(x.y - M) * invL;
        x.z = __expf(x.z - M) * invL;
        x.w = __expf(x.w - M) * invL;
        a4[i * 256 + tid] = x;
    }
}

extern "C" void kernel_launch(void* const* d_in, const int* in_sizes, int n_in,
                              void* d_out, int out_size) {
    const float* dec = (const float*)d_in[0];   // (32, 1024)
    const float* enc = (const float*)d_in[1];   // (32, 4096, 1024)
    float* out = (float*)d_out;                 // [context (32*1024) | attn (32*4096)]
    float* ctx_out  = out;
    float* attn_out = out + (size_t)B_ * H_;

    cudaFuncSetAttribute(attn_fused, cudaFuncAttributeMaxDynamicSharedMemorySize,
                         SMEM_BYTES);

    dim3 grid(CHUNKS, B_);
    attn_fused<<<grid, 256, SMEM_BYTES>>>(dec, enc, ctx_out, attn_out);
}

// round 13
// speedup vs baseline: 1.0926x; 1.0512x over previous
#include <cuda_runtime.h>
#include <cuda_bf16.h>
#include <cstdint>
#include <math_constants.h>

// Problem shape (fixed per reference)
#define B_  32
#define S_  4096
#define H_  1024
#define CHUNKS 16             // s-chunks per batch (best measured config)
#define SC  (S_ / CHUNKS)     // 256 rows per chunk
#define TR  8                 // rows per tile (one row per warp)
#define NT  (SC / TR)         // 32 tiles per chunk
#define NS  3                 // pipeline stages
#define TILE_BYTES (TR * H_ * 4)       // 32 KB
#define STAGE_FLOATS (TR * H_)

// SMEM layout (bytes)
#define SM_STAGES_OFF 0
#define SM_DEC_OFF    (NS * TILE_BYTES)              // 98304
#define SM_ML_OFF     (SM_DEC_OFF + H_ * 4)          // m[8], l[8]
#define SM_FLAG_OFF   (SM_ML_OFF + 64)               // int flag
#define SM_MBAR_OFF   (SM_FLAG_OFF + 8)
#define SMEM_BYTES    (SM_MBAR_OFF + NS * 8 + 8)

// Scratch (__device__ globals: allocation-free)
__device__ float g_m[B_ * CHUNKS];
__device__ float g_l[B_ * CHUNKS];
__device__ float g_ctx[(size_t)B_ * CHUNKS * H_];
__device__ int   g_cnt[B_];   // zero-initialized; reset in-kernel each launch

__device__ __forceinline__ uint32_t smem_u32(const void* p) {
    uint32_t a;
    asm("{ .reg .u64 t; cvta.to.shared.u64 t, %1; cvt.u32.u64 %0, t; }"
        : "=r"(a) : "l"(p));
    return a;
}

__device__ __forceinline__ void mbar_init(uint32_t mbar, uint32_t cnt) {
    asm volatile("mbarrier.init.shared.b64 [%0], %1;" :: "r"(mbar), "r"(cnt) : "memory");
}
__device__ __forceinline__ void mbar_expect_tx(uint32_t mbar, uint32_t bytes) {
    asm volatile("mbarrier.arrive.expect_tx.shared.b64 _, [%0], %1;"
                 :: "r"(mbar), "r"(bytes) : "memory");
}
__device__ __forceinline__ void mbar_wait(uint32_t mbar, uint32_t parity) {
    uint32_t done;
    asm volatile(
        "{\n\t"
        ".reg .pred p;\n\t"
        "mbarrier.try_wait.parity.acquire.cta.shared::cta.b64 p, [%1], %2;\n\t"
        "selp.b32 %0, 1, 0, p;\n\t"
        "}" : "=r"(done) : "r"(mbar), "r"(parity) : "memory");
    if (!done) {
        asm volatile(
            "{\n\t"
            ".reg .pred P1;\n\t"
            "WAIT_LOOP_%=:\n\t"
            "mbarrier.try_wait.parity.acquire.cta.shared::cta.b64 P1, [%0], %1, 0x989680;\n\t"
            "@P1 bra.uni WAIT_DONE_%=;\n\t"
            "bra.uni WAIT_LOOP_%=;\n\t"
            "WAIT_DONE_%=:\n\t"
            "}" :: "r"(mbar), "r"(parity) : "memory");
    }
}
// bulk load with L2 evict_first hint (enc is pure streaming, no reuse)
__device__ __forceinline__ void bulk_g2s_stream(uint32_t dst, const void* src,
                                                uint32_t bytes, uint32_t mbar,
                                                uint64_t pol) {
    asm volatile(
        "cp.async.bulk.shared::cluster.global.mbarrier::complete_tx::bytes.L2::cache_hint "
        "[%0], [%1], %2, [%3], %4;"
        :: "r"(dst), "l"(src), "r"(bytes), "r"(mbar), "l"(pol) : "memory");
}

// ---------------------------------------------------------------------------
// Single fused kernel (R8 structure): streaming online-softmax pass +
// last-CTA-per-batch combine (threadfence-reduction pattern).
// Barrier placed AFTER the score consumes v (measured-best ordering).
// ---------------------------------------------------------------------------
__global__ void __launch_bounds__(256, 2)
attn_fused(const float* __restrict__ dec,
           const float* __restrict__ enc,
           float* __restrict__ ctx_out,       // d_out
           float* __restrict__ attn_out)      // d_out + B_*H_
{
    extern __shared__ __align__(16) char smem[];
    float* s_stage = (float*)(smem + SM_STAGES_OFF);
    float* s_dec   = (float*)(smem + SM_DEC_OFF);
    float* s_m     = (float*)(smem + SM_ML_OFF);
    float* s_l     = s_m + TR;
    int*   s_last  = (int*)(smem + SM_FLAG_OFF);
    uint32_t smbase = smem_u32(smem);
    uint32_t mbar0  = smbase + SM_MBAR_OFF;

    const int b     = blockIdx.y;
    const int chunk = blockIdx.x;
    const int tid   = threadIdx.x;
    const int w     = tid >> 5;
    const int lid   = tid & 31;

    const float* encB = enc + ((size_t)b * S_ + (size_t)chunk * SC) * H_;

    uint64_t pol;
    asm("createpolicy.fractional.L2::evict_first.b64 %0, 1.0;" : "=l"(pol));

    if (tid == 0) {
        #pragma unroll
        for (int s = 0; s < NS; s++) mbar_init(mbar0 + 8u * s, 1);
    }
    ((float4*)s_dec)[tid] = ((const float4*)(dec + (size_t)b * H_))[tid];
    __syncthreads();

    if (tid == 0) {
        #pragma unroll
        for (int s = 0; s < NS; s++) {
            mbar_expect_tx(mbar0 + 8u * s, TILE_BYTES);
            bulk_g2s_stream(smbase + SM_STAGES_OFF + s * TILE_BYTES,
                            encB + (size_t)s * TR * H_, TILE_BYTES,
                            mbar0 + 8u * s, pol);
        }
    }

    // decoder slice in registers
    float4 dreg[8];
    #pragma unroll
    for (int k = 0; k < 8; k++) dreg[k] = ((float4*)s_dec)[k * 32 + lid];

    float4 acc[8];
    #pragma unroll
    for (int k = 0; k < 8; k++) acc[k] = make_float4(0.f, 0.f, 0.f, 0.f);
    float m = -CUDART_INF_F;
    float l = 0.f;

    for (int t = 0; t < NT; t++) {
        const int st = t % NS;
        const uint32_t ph = (uint32_t)((t / NS) & 1);
        const uint32_t mbar = mbar0 + 8u * st;
        mbar_wait(mbar, ph);

        // warp w's row of this tile, into registers (single SMEM read)
        float4* er = (float4*)(s_stage + st * STAGE_FLOATS) + w * 256;
        float4 v[8];
        #pragma unroll
        for (int k = 0; k < 8; k++) v[k] = er[k * 32 + lid];

        float p = 0.f;
        #pragma unroll
        for (int k = 0; k < 8; k++) {
            p = fmaf(dreg[k].x, v[k].x, p);
            p = fmaf(dreg[k].y, v[k].y, p);
            p = fmaf(dreg[k].z, v[k].z, p);
            p = fmaf(dreg[k].w, v[k].w, p);
        }
        #pragma unroll
        for (int off = 16; off > 0; off >>= 1)
            p += __shfl_xor_sync(0xFFFFFFFFu, p, off);

        __syncthreads();   // all warps' loads done -> stage reusable
        if (tid == 0 && (t + NS) < NT) {
            mbar_expect_tx(mbar, TILE_BYTES);
            bulk_g2s_stream(smbase + SM_STAGES_OFF + st * TILE_BYTES,
                            encB + (size_t)(t + NS) * TR * H_, TILE_BYTES,
                            mbar, pol);
        }

        if (lid == 0)
            attn_out[(size_t)b * S_ + chunk * SC + t * TR + w] = p;   // raw score

        // per-warp online softmax update (overlaps with TMA refill)
        if (p > m) {
            float scale = __expf(m - p);
            m = p;
            l *= scale;
            #pragma unroll
            for (int k = 0; k < 8; k++) {
                acc[k].x *= scale; acc[k].y *= scale;
                acc[k].z *= scale; acc[k].w *= scale;
            }
        }
        float wgt = __expf(p - m);
        l += wgt;
        #pragma unroll
        for (int k = 0; k < 8; k++) {
            acc[k].x = fmaf(wgt, v[k].x, acc[k].x);
            acc[k].y = fmaf(wgt, v[k].y, acc[k].y);
            acc[k].z = fmaf(wgt, v[k].z, acc[k].z);
            acc[k].w = fmaf(wgt, v[k].w, acc[k].w);
        }
    }

    // ---- merge the 8 per-warp (m, l, acc) triples ----
    if (lid == 0) { s_m[w] = m; s_l[w] = l; }
    __syncthreads();

    float Mc = -CUDART_INF_F;
    #pragma unroll
    for (int r = 0; r < TR; r++) Mc = fmaxf(Mc, s_m[r]);
    float Lc = 0.f;
    #pragma unroll
    for (int r = 0; r < TR; r++) Lc += s_l[r] * __expf(s_m[r] - Mc);
    float myscale = __expf(m - Mc);   // uniform within warp

    float4* dst = (float4*)s_stage + w * 256;
    #pragma unroll
    for (int k = 0; k < 8; k++) {
        float4 a = acc[k];
        a.x *= myscale; a.y *= myscale; a.z *= myscale; a.w *= myscale;
        dst[k * 32 + lid] = a;
    }
    __syncthreads();

    float4* sb = (float4*)s_stage;
    float4 s = make_float4(0.f, 0.f, 0.f, 0.f);
    #pragma unroll
    for (int r = 0; r < TR; r++) {
        float4 x = sb[r * 256 + tid];
        s.x += x.x; s.y += x.y; s.z += x.z; s.w += x.w;
    }
    const int cid = b * CHUNKS + chunk;
    ((float4*)(g_ctx + (size_t)cid * H_))[tid] = s;
    if (tid == 0) { g_m[cid] = Mc; g_l[cid] = Lc; }

    // ---- last CTA of this batch performs the combine ----
    __threadfence();   // release partials + raw scores
    if (tid == 0) {
        int old = atomicAdd(&g_cnt[b], 1);
        *s_last = (old == CHUNKS - 1);
    }
    __syncthreads();
    if (!*s_last) return;

    __threadfence();   // acquire all CTAs' partials/scores
    if (tid == 0) g_cnt[b] = 0;   // reset for next graph replay

    float M = -CUDART_INF_F;
    #pragma unroll
    for (int c = 0; c < CHUNKS; c++) M = fmaxf(M, g_m[b * CHUNKS + c]);
    float L = 0.f;
    #pragma unroll
    for (int c = 0; c < CHUNKS; c++)
        L += g_l[b * CHUNKS + c] * __expf(g_m[b * CHUNKS + c] - M);
    const float invL = 1.0f / L;

    // context: 1024 floats = 256 float4, one per thread
    float4 cs = make_float4(0.f, 0.f, 0.f, 0.f);
    #pragma unroll
    for (int c = 0; c < CHUNKS; c++) {
        float ef = __expf(g_m[b * CHUNKS + c] - M);
        float4 v = ((const float4*)(g_ctx + (size_t)(b * CHUNKS + c) * H_))[tid];
        cs.x = fmaf(ef, v.x, cs.x);
        cs.y = fmaf(ef, v.y, cs.y);
        cs.z = fmaf(ef, v.z, cs.z);
        cs.w = fmaf(ef, v.w, cs.w);
    }
    cs.x *= invL; cs.y *= invL; cs.z *= invL; cs.w *= invL;
    ((float4*)(ctx_out + (size_t)b * H_))[tid] = cs;

    // attn: normalize this batch's 4096 raw scores (1024 float4, 4/thread)
    float4* a4 = (float4*)(attn_out + (size_t)b * S_);
    #pragma unroll
    for (int i = 0; i < 4; i++) {
        float4 x = a4[i * 256 + tid];
        x.x = __expf(x.x - M) * invL;
        x.y = __expf(x.y - M) * invL;
        x.z = __expf(x.z - M) * invL;
        x.w = __expf(x.w - M) * invL;
        a4[i * 256 + tid] = x;
    }
}

extern "C" void kernel_launch(void* const* d_in, const int* in_sizes, int n_in,
                              void* d_out, int out_size) {
    const float* dec = (const float*)d_in[0];   // (32, 1024)
    const float* enc = (const float*)d_in[1];   // (32, 4096, 1024)
    float* out = (float*)d_out;                 // [context (32*1024) | attn (32*4096)]
    float* ctx_out  = out;
    float* attn_out = out + (size_t)B_ * H_;

    cudaFuncSetAttribute(attn_fused, cudaFuncAttributeMaxDynamicSharedMemorySize,
                         SMEM_BYTES);

    dim3 grid(CHUNKS, B_);
    attn_fused<<<grid, 256, SMEM_BYTES>>>(dec, enc, ctx_out, attn_out);
}

// round 15
// speedup vs baseline: 1.1136x; 1.0192x over previous
#include <cuda_runtime.h>
#include <cuda_bf16.h>
#include <cstdint>
#include <math_constants.h>

// Problem shape (fixed per reference)
#define B_  32
#define S_  4096
#define H_  1024
#define CHUNKS 16             // s-chunks per batch (best measured config)
#define SC  (S_ / CHUNKS)     // 256 rows per chunk
#define TR  8                 // rows per tile (one row per warp)
#define NT  (SC / TR)         // 32 tiles per chunk
#define NS  3                 // pipeline stages
#define TILE_BYTES (TR * H_ * 4)       // 32 KB
#define STAGE_FLOATS (TR * H_)
#define PROD_TID 224          // warp 7 lane 0: highest arbiter priority

// SMEM layout (bytes)
#define SM_STAGES_OFF 0
#define SM_DEC_OFF    (NS * TILE_BYTES)              // 98304
#define SM_ML_OFF     (SM_DEC_OFF + H_ * 4)          // m[8], l[8]
#define SM_FLAG_OFF   (SM_ML_OFF + 64)               // int flag
#define SM_MBAR_OFF   (SM_FLAG_OFF + 8)
#define SMEM_BYTES    (SM_MBAR_OFF + NS * 8 + 8)

// Scratch (__device__ globals: allocation-free)
__device__ float g_m[B_ * CHUNKS];
__device__ float g_l[B_ * CHUNKS];
__device__ float g_ctx[(size_t)B_ * CHUNKS * H_];
__device__ int   g_cnt[B_];   // zero-initialized; reset in-kernel each launch

__device__ __forceinline__ uint32_t smem_u32(const void* p) {
    uint32_t a;
    asm("{ .reg .u64 t; cvta.to.shared.u64 t, %1; cvt.u32.u64 %0, t; }"
        : "=r"(a) : "l"(p));
    return a;
}

__device__ __forceinline__ void mbar_init(uint32_t mbar, uint32_t cnt) {
    asm volatile("mbarrier.init.shared.b64 [%0], %1;" :: "r"(mbar), "r"(cnt) : "memory");
}
__device__ __forceinline__ void mbar_expect_tx(uint32_t mbar, uint32_t bytes) {
    asm volatile("mbarrier.arrive.expect_tx.shared.b64 _, [%0], %1;"
                 :: "r"(mbar), "r"(bytes) : "memory");
}
__device__ __forceinline__ void mbar_wait(uint32_t mbar, uint32_t parity) {
    uint32_t done;
    asm volatile(
        "{\n\t"
        ".reg .pred p;\n\t"
        "mbarrier.try_wait.parity.acquire.cta.shared::cta.b64 p, [%1], %2;\n\t"
        "selp.b32 %0, 1, 0, p;\n\t"
        "}" : "=r"(done) : "r"(mbar), "r"(parity) : "memory");
    if (!done) {
        asm volatile(
            "{\n\t"
            ".reg .pred P1;\n\t"
            "WAIT_LOOP_%=:\n\t"
            "mbarrier.try_wait.parity.acquire.cta.shared::cta.b64 P1, [%0], %1, 0x989680;\n\t"
            "@P1 bra.uni WAIT_DONE_%=;\n\t"
            "bra.uni WAIT_LOOP_%=;\n\t"
            "WAIT_DONE_%=:\n\t"
            "}" :: "r"(mbar), "r"(parity) : "memory");
    }
}
// bulk load with L2 evict_first hint (enc is pure streaming, no reuse)
__device__ __forceinline__ void bulk_g2s_stream(uint32_t dst, const void* src,
                                                uint32_t bytes, uint32_t mbar,
                                                uint64_t pol) {
    asm volatile(
        "cp.async.bulk.shared::cluster.global.mbarrier::complete_tx::bytes.L2::cache_hint "
        "[%0], [%1], %2, [%3], %4;"
        :: "r"(dst), "l"(src), "r"(bytes), "r"(mbar), "l"(pol) : "memory");
}

// ---------------------------------------------------------------------------
// Single fused kernel (R8 structure): streaming online-softmax pass +
// last-CTA-per-batch combine. Refills issued by warp 7 (highest arbiter
// priority) so the producer path isn't queued behind 7 consumer warps.
// ---------------------------------------------------------------------------
__global__ void __launch_bounds__(256, 2)
attn_fused(const float* __restrict__ dec,
           const float* __restrict__ enc,
           float* __restrict__ ctx_out,       // d_out
           float* __restrict__ attn_out)      // d_out + B_*H_
{
    extern __shared__ __align__(16) char smem[];
    float* s_stage = (float*)(smem + SM_STAGES_OFF);
    float* s_dec   = (float*)(smem + SM_DEC_OFF);
    float* s_m     = (float*)(smem + SM_ML_OFF);
    float* s_l     = s_m + TR;
    int*   s_last  = (int*)(smem + SM_FLAG_OFF);
    uint32_t smbase = smem_u32(smem);
    uint32_t mbar0  = smbase + SM_MBAR_OFF;

    const int b     = blockIdx.y;
    const int chunk = blockIdx.x;
    const int tid   = threadIdx.x;
    const int w     = tid >> 5;
    const int lid   = tid & 31;

    const float* encB = enc + ((size_t)b * S_ + (size_t)chunk * SC) * H_;

    uint64_t pol;
    asm("createpolicy.fractional.L2::evict_first.b64 %0, 1.0;" : "=l"(pol));

    if (tid == PROD_TID) {
        #pragma unroll
        for (int s = 0; s < NS; s++) mbar_init(mbar0 + 8u * s, 1);
    }
    ((float4*)s_dec)[tid] = ((const float4*)(dec + (size_t)b * H_))[tid];
    __syncthreads();

    if (tid == PROD_TID) {
        #pragma unroll
        for (int s = 0; s < NS; s++) {
            mbar_expect_tx(mbar0 + 8u * s, TILE_BYTES);
            bulk_g2s_stream(smbase + SM_STAGES_OFF + s * TILE_BYTES,
                            encB + (size_t)s * TR * H_, TILE_BYTES,
                            mbar0 + 8u * s, pol);
        }
    }

    // decoder slice in registers
    float4 dreg[8];
    #pragma unroll
    for (int k = 0; k < 8; k++) dreg[k] = ((float4*)s_dec)[k * 32 + lid];

    float4 acc[8];
    #pragma unroll
    for (int k = 0; k < 8; k++) acc[k] = make_float4(0.f, 0.f, 0.f, 0.f);
    float m = -CUDART_INF_F;
    float l = 0.f;

    for (int t = 0; t < NT; t++) {
        const int st = t % NS;
        const uint32_t ph = (uint32_t)((t / NS) & 1);
        const uint32_t mbar = mbar0 + 8u * st;
        mbar_wait(mbar, ph);

        // warp w's row of this tile, into registers (single SMEM read)
        float4* er = (float4*)(s_stage + st * STAGE_FLOATS) + w * 256;
        float4 v[8];
        #pragma unroll
        for (int k = 0; k < 8; k++) v[k] = er[k * 32 + lid];

        float p = 0.f;
        #pragma unroll
        for (int k = 0; k < 8; k++) {
            p = fmaf(dreg[k].x, v[k].x, p);
            p = fmaf(dreg[k].y, v[k].y, p);
            p = fmaf(dreg[k].z, v[k].z, p);
            p = fmaf(dreg[k].w, v[k].w, p);
        }
        #pragma unroll
        for (int off = 16; off > 0; off >>= 1)
            p += __shfl_xor_sync(0xFFFFFFFFu, p, off);

        __syncthreads();   // all warps' loads done -> stage reusable
        if (tid == PROD_TID && (t + NS) < NT) {
            mbar_expect_tx(mbar, TILE_BYTES);
            bulk_g2s_stream(smbase + SM_STAGES_OFF + st * TILE_BYTES,
                            encB + (size_t)(t + NS) * TR * H_, TILE_BYTES,
                            mbar, pol);
        }

        if (lid == 0)
            attn_out[(size_t)b * S_ + chunk * SC + t * TR + w] = p;   // raw score

        // per-warp online softmax update (overlaps with TMA refill)
        if (p > m) {
            float scale = __expf(m - p);
            m = p;
            l *= scale;
            #pragma unroll
            for (int k = 0; k < 8; k++) {
                acc[k].x *= scale; acc[k].y *= scale;
                acc[k].z *= scale; acc[k].w *= scale;
            }
        }
        float wgt = __expf(p - m);
        l += wgt;
        #pragma unroll
        for (int k = 0; k < 8; k++) {
            acc[k].x = fmaf(wgt, v[k].x, acc[k].x);
            acc[k].y = fmaf(wgt, v[k].y, acc[k].y);
            acc[k].z = fmaf(wgt, v[k].z, acc[k].z);
            acc[k].w = fmaf(wgt, v[k].w, acc[k].w);
        }
    }

    // ---- merge the 8 per-warp (m, l, acc) triples ----
    if (lid == 0) { s_m[w] = m; s_l[w] = l; }
    __syncthreads();

    float Mc = -CUDART_INF_F;
    #pragma unroll
    for (int r = 0; r < TR; r++) Mc = fmaxf(Mc, s_m[r]);
    float Lc = 0.f;
    #pragma unroll
    for (int r = 0; r < TR; r++) Lc += s_l[r] * __expf(s_m[r] - Mc);
    float myscale = __expf(m - Mc);   // uniform within warp

    float4* dst = (float4*)s_stage + w * 256;
    #pragma unroll
    for (int k = 0; k < 8; k++) {
        float4 a = acc[k];
        a.x *= myscale; a.y *= myscale; a.z *= myscale; a.w *= myscale;
        dst[k * 32 + lid] = a;
    }
    __syncthreads();

    float4* sb = (float4*)s_stage;
    float4 s = make_float4(0.f, 0.f, 0.f, 0.f);
    #pragma unroll
    for (int r = 0; r < TR; r++) {
        float4 x = sb[r * 256 + tid];
        s.x += x.x; s.y += x.y; s.z += x.z; s.w += x.w;
    }
    const int cid = b * CHUNKS + chunk;
    ((float4*)(g_ctx + (size_t)cid * H_))[tid] = s;
    if (tid == 0) { g_m[cid] = Mc; g_l[cid] = Lc; }

    // ---- last CTA of this batch performs the combine ----
    __threadfence();   // release partials + raw scores
    if (tid == 0) {
        int old = atomicAdd(&g_cnt[b], 1);
        *s_last = (old == CHUNKS - 1);
    }
    __syncthreads();
    if (!*s_last) return;

    __threadfence();   // acquire all CTAs' partials/scores
    if (tid == 0) g_cnt[b] = 0;   // reset for next graph replay

    float M = -CUDART_INF_F;
    #pragma unroll
    for (int c = 0; c < CHUNKS; c++) M = fmaxf(M, g_m[b * CHUNKS + c]);
    float L = 0.f;
    #pragma unroll
    for (int c = 0; c < CHUNKS; c++)
        L += g_l[b * CHUNKS + c] * __expf(g_m[b * CHUNKS + c] - M);
    const float invL = 1.0f / L;

    // context: 1024 floats = 256 float4, one per thread
    float4 cs = make_float4(0.f, 0.f, 0.f, 0.f);
    #pragma unroll
    for (int c = 0; c < CHUNKS; c++) {
        float ef = __expf(g_m[b * CHUNKS + c] - M);
        float4 v = ((const float4*)(g_ctx + (size_t)(b * CHUNKS + c) * H_))[tid];
        cs.x = fmaf(ef, v.x, cs.x);
        cs.y = fmaf(ef, v.y, cs.y);
        cs.z = fmaf(ef, v.z, cs.z);
        cs.w = fmaf(ef, v.w, cs.w);
    }
    cs.x *= invL; cs.y *= invL; cs.z *= invL; cs.w *= invL;
    ((float4*)(ctx_out + (size_t)b * H_))[tid] = cs;

    // attn: normalize this batch's 4096 raw scores (1024 float4, 4/thread)
    float4* a4 = (float4*)(attn_out + (size_t)b * S_);
    #pragma unroll
    for (int i = 0; i < 4; i++) {
        float4 x = a4[i * 256 + tid];
        x.x = __expf(x.x - M) * invL;
        x.y = __expf(x.y - M) * invL;
        x.z = __expf(x.z - M) * invL;
        x.w = __expf(x.w - M) * invL;
        a4[i * 256 + tid] = x;
    }
}

extern "C" void kernel_launch(void* const* d_in, const int* in_sizes, int n_in,
                              void* d_out, int out_size) {
    const float* dec = (const float*)d_in[0];   // (32, 1024)
    const float* enc = (const float*)d_in[1];   // (32, 4096, 1024)
    float* out = (float*)d_out;                 // [context (32*1024) | attn (32*4096)]
    float* ctx_out  = out;
    float* attn_out = out + (size_t)B_ * H_;

    cudaFuncSetAttribute(attn_fused, cudaFuncAttributeMaxDynamicSharedMemorySize,
                         SMEM_BYTES);

    dim3 grid(CHUNKS, B_);
    attn_fused<<<grid, 256, SMEM_BYTES>>>(dec, enc, ctx_out, attn_out);
}

// round 16
// speedup vs baseline: 1.1363x; 1.0204x over previous
#include <cuda_runtime.h>
#include <cuda_bf16.h>
#include <cstdint>
#include <math_constants.h>

// Problem shape (fixed per reference)
#define B_  32
#define S_  4096
#define H_  1024
#define CHUNKS 16             // s-chunks per batch (best measured config)
#define SC  (S_ / CHUNKS)     // 256 rows per chunk
#define TR  8                 // rows per tile (one row per warp)
#define NT  (SC / TR)         // 32 tiles per chunk
#define NS  3                 // pipeline stages
#define TILE_BYTES (TR * H_ * 4)       // 32 KB
#define STAGE_FLOATS (TR * H_)
#define PROD_TID 224          // warp 7 lane 0: highest arbiter priority

// SMEM layout (bytes)
#define SM_STAGES_OFF 0
#define SM_DEC_OFF    (NS * TILE_BYTES)              // 98304
#define SM_ML_OFF     (SM_DEC_OFF + H_ * 4)          // m[8], l[8]
#define SM_SCORE_OFF  (SM_ML_OFF + 64)               // 256 floats (chunk scores)
#define SM_FLAG_OFF   (SM_SCORE_OFF + SC * 4)        // int flag
#define SM_MBAR_OFF   (SM_FLAG_OFF + 8)
#define SMEM_BYTES    (SM_MBAR_OFF + NS * 8 + 8)

// Scratch (__device__ globals: allocation-free)
__device__ float g_m[B_ * CHUNKS];
__device__ float g_l[B_ * CHUNKS];
__device__ float g_ctx[(size_t)B_ * CHUNKS * H_];
__device__ int   g_cnt[B_];   // zero-initialized; reset in-kernel each launch

__device__ __forceinline__ uint32_t smem_u32(const void* p) {
    uint32_t a;
    asm("{ .reg .u64 t; cvta.to.shared.u64 t, %1; cvt.u32.u64 %0, t; }"
        : "=r"(a) : "l"(p));
    return a;
}

__device__ __forceinline__ void mbar_init(uint32_t mbar, uint32_t cnt) {
    asm volatile("mbarrier.init.shared.b64 [%0], %1;" :: "r"(mbar), "r"(cnt) : "memory");
}
__device__ __forceinline__ void mbar_expect_tx(uint32_t mbar, uint32_t bytes) {
    asm volatile("mbarrier.arrive.expect_tx.shared.b64 _, [%0], %1;"
                 :: "r"(mbar), "r"(bytes) : "memory");
}
__device__ __forceinline__ void mbar_wait(uint32_t mbar, uint32_t parity) {
    uint32_t done;
    asm volatile(
        "{\n\t"
        ".reg .pred p;\n\t"
        "mbarrier.try_wait.parity.acquire.cta.shared::cta.b64 p, [%1], %2;\n\t"
        "selp.b32 %0, 1, 0, p;\n\t"
        "}" : "=r"(done) : "r"(mbar), "r"(parity) : "memory");
    if (!done) {
        asm volatile(
            "{\n\t"
            ".reg .pred P1;\n\t"
            "WAIT_LOOP_%=:\n\t"
            "mbarrier.try_wait.parity.acquire.cta.shared::cta.b64 P1, [%0], %1, 0x989680;\n\t"
            "@P1 bra.uni WAIT_DONE_%=;\n\t"
            "bra.uni WAIT_LOOP_%=;\n\t"
            "WAIT_DONE_%=:\n\t"
            "}" :: "r"(mbar), "r"(parity) : "memory");
    }
}
// bulk load with L2 evict_first hint (enc is pure streaming, no reuse)
__device__ __forceinline__ void bulk_g2s_stream(uint32_t dst, const void* src,
                                                uint32_t bytes, uint32_t mbar,
                                                uint64_t pol) {
    asm volatile(
        "cp.async.bulk.shared::cluster.global.mbarrier::complete_tx::bytes.L2::cache_hint "
        "[%0], [%1], %2, [%3], %4;"
        :: "r"(dst), "l"(src), "r"(bytes), "r"(mbar), "l"(pol) : "memory");
}

// ---------------------------------------------------------------------------
// Single fused kernel (R8 structure): streaming online-softmax pass +
// last-CTA-per-batch combine. Raw scores buffered in SMEM and written
// coalesced at chunk end (no scattered 4B STG in the hot loop).
// ---------------------------------------------------------------------------
__global__ void __launch_bounds__(256, 2)
attn_fused(const float* __restrict__ dec,
           const float* __restrict__ enc,
           float* __restrict__ ctx_out,       // d_out
           float* __restrict__ attn_out)      // d_out + B_*H_
{
    extern __shared__ __align__(16) char smem[];
    float* s_stage = (float*)(smem + SM_STAGES_OFF);
    float* s_dec   = (float*)(smem + SM_DEC_OFF);
    float* s_m     = (float*)(smem + SM_ML_OFF);
    float* s_l     = s_m + TR;
    float* s_score = (float*)(smem + SM_SCORE_OFF);
    int*   s_last  = (int*)(smem + SM_FLAG_OFF);
    uint32_t smbase = smem_u32(smem);
    uint32_t mbar0  = smbase + SM_MBAR_OFF;

    const int b     = blockIdx.y;
    const int chunk = blockIdx.x;
    const int tid   = threadIdx.x;
    const int w     = tid >> 5;
    const int lid   = tid & 31;

    const float* encB = enc + ((size_t)b * S_ + (size_t)chunk * SC) * H_;

    uint64_t pol;
    asm("createpolicy.fractional.L2::evict_first.b64 %0, 1.0;" : "=l"(pol));

    if (tid == PROD_TID) {
        #pragma unroll
        for (int s = 0; s < NS; s++) mbar_init(mbar0 + 8u * s, 1);
    }
    ((float4*)s_dec)[tid] = ((const float4*)(dec + (size_t)b * H_))[tid];
    __syncthreads();

    if (tid == PROD_TID) {
        #pragma unroll
        for (int s = 0; s < NS; s++) {
            mbar_expect_tx(mbar0 + 8u * s, TILE_BYTES);
            bulk_g2s_stream(smbase + SM_STAGES_OFF + s * TILE_BYTES,
                            encB + (size_t)s * TR * H_, TILE_BYTES,
                            mbar0 + 8u * s, pol);
        }
    }

    // decoder slice in registers
    float4 dreg[8];
    #pragma unroll
    for (int k = 0; k < 8; k++) dreg[k] = ((float4*)s_dec)[k * 32 + lid];

    float4 acc[8];
    #pragma unroll
    for (int k = 0; k < 8; k++) acc[k] = make_float4(0.f, 0.f, 0.f, 0.f);
    float m = -CUDART_INF_F;
    float l = 0.f;

    for (int t = 0; t < NT; t++) {
        const int st = t % NS;
        const uint32_t ph = (uint32_t)((t / NS) & 1);
        const uint32_t mbar = mbar0 + 8u * st;
        mbar_wait(mbar, ph);

        // warp w's row of this tile, into registers (single SMEM read)
        float4* er = (float4*)(s_stage + st * STAGE_FLOATS) + w * 256;
        float4 v[8];
        #pragma unroll
        for (int k = 0; k < 8; k++) v[k] = er[k * 32 + lid];

        float p = 0.f;
        #pragma unroll
        for (int k = 0; k < 8; k++) {
            p = fmaf(dreg[k].x, v[k].x, p);
            p = fmaf(dreg[k].y, v[k].y, p);
            p = fmaf(dreg[k].z, v[k].z, p);
            p = fmaf(dreg[k].w, v[k].w, p);
        }
        #pragma unroll
        for (int off = 16; off > 0; off >>= 1)
            p += __shfl_xor_sync(0xFFFFFFFFu, p, off);

        __syncthreads();   // all warps' loads done -> stage reusable
        if (tid == PROD_TID && (t + NS) < NT) {
            mbar_expect_tx(mbar, TILE_BYTES);
            bulk_g2s_stream(smbase + SM_STAGES_OFF + st * TILE_BYTES,
                            encB + (size_t)(t + NS) * TR * H_, TILE_BYTES,
                            mbar, pol);
        }

        if (lid == 0)
            s_score[t * TR + w] = p;   // SMEM buffer, flushed coalesced at end

        // per-warp online softmax update (overlaps with TMA refill)
        if (p > m) {
            float scale = __expf(m - p);
            m = p;
            l *= scale;
            #pragma unroll
            for (int k = 0; k < 8; k++) {
                acc[k].x *= scale; acc[k].y *= scale;
                acc[k].z *= scale; acc[k].w *= scale;
            }
        }
        float wgt = __expf(p - m);
        l += wgt;
        #pragma unroll
        for (int k = 0; k < 8; k++) {
            acc[k].x = fmaf(wgt, v[k].x, acc[k].x);
            acc[k].y = fmaf(wgt, v[k].y, acc[k].y);
            acc[k].z = fmaf(wgt, v[k].z, acc[k].z);
            acc[k].w = fmaf(wgt, v[k].w, acc[k].w);
        }
    }

    // ---- merge the 8 per-warp (m, l, acc) triples ----
    if (lid == 0) { s_m[w] = m; s_l[w] = l; }
    __syncthreads();

    // flush the chunk's 256 raw scores coalesced (64 x STG.128)
    if (tid < SC / 4)
        ((float4*)(attn_out + (size_t)b * S_ + (size_t)chunk * SC))[tid] =
            ((float4*)s_score)[tid];

    float Mc = -CUDART_INF_F;
    #pragma unroll
    for (int r = 0; r < TR; r++) Mc = fmaxf(Mc, s_m[r]);
    float Lc = 0.f;
    #pragma unroll
    for (int r = 0; r < TR; r++) Lc += s_l[r] * __expf(s_m[r] - Mc);
    float myscale = __expf(m - Mc);   // uniform within warp

    float4* dst = (float4*)s_stage + w * 256;
    #pragma unroll
    for (int k = 0; k < 8; k++) {
        float4 a = acc[k];
        a.x *= myscale; a.y *= myscale; a.z *= myscale; a.w *= myscale;
        dst[k * 32 + lid] = a;
    }
    __syncthreads();

    float4* sb = (float4*)s_stage;
    float4 s = make_float4(0.f, 0.f, 0.f, 0.f);
    #pragma unroll
    for (int r = 0; r < TR; r++) {
        float4 x = sb[r * 256 + tid];
        s.x += x.x; s.y += x.y; s.z += x.z; s.w += x.w;
    }
    const int cid = b * CHUNKS + chunk;
    ((float4*)(g_ctx + (size_t)cid * H_))[tid] = s;
    if (tid == 0) { g_m[cid] = Mc; g_l[cid] = Lc; }

    // ---- last CTA of this batch performs the combine ----
    __threadfence();   // release partials + raw scores
    if (tid == 0) {
        int old = atomicAdd(&g_cnt[b], 1);
        *s_last = (old == CHUNKS - 1);
    }
    __syncthreads();
    if (!*s_last) return;

    __threadfence();   // acquire all CTAs' partials/scores
    if (tid == 0) g_cnt[b] = 0;   // reset for next graph replay

    float M = -CUDART_INF_F;
    #pragma unroll
    for (int c = 0; c < CHUNKS; c++) M = fmaxf(M, g_m[b * CHUNKS + c]);
    float L = 0.f;
    #pragma unroll
    for (int c = 0; c < CHUNKS; c++)
        L += g_l[b * CHUNKS + c] * __expf(g_m[b * CHUNKS + c] - M);
    const float invL = 1.0f / L;

    // context: 1024 floats = 256 float4, one per thread
    float4 cs = make_float4(0.f, 0.f, 0.f, 0.f);
    #pragma unroll
    for (int c = 0; c < CHUNKS; c++) {
        float ef = __expf(g_m[b * CHUNKS + c] - M);
        float4 v = ((const float4*)(g_ctx + (size_t)(b * CHUNKS + c) * H_))[tid];
        cs.x = fmaf(ef, v.x, cs.x);
        cs.y = fmaf(ef, v.y, cs.y);
        cs.z = fmaf(ef, v.z, cs.z);
        cs.w = fmaf(ef, v.w, cs.w);
    }
    cs.x *= invL; cs.y *= invL; cs.z *= invL; cs.w *= invL;
    ((float4*)(ctx_out + (size_t)b * H_))[tid] = cs;

    // attn: normalize this batch's 4096 raw scores (1024 float4, 4/thread)
    float4* a4 = (float4*)(attn_out + (size_t)b * S_);
    #pragma unroll
    for (int i = 0; i < 4; i++) {
        float4 x = a4[i * 256 + tid];
        x.x = __expf(x.x - M) * invL;
        x.y = __expf(x.y - M) * invL;
        x.z = __expf(x.z - M) * invL;
        x.w = __expf(x.w - M) * invL;
        a4[i * 256 + tid] = x;
    }
}

extern "C" void kernel_launch(void* const* d_in, const int* in_sizes, int n_in,
                              void* d_out, int out_size) {
    const float* dec = (const float*)d_in[0];   // (32, 1024)
    const float* enc = (const float*)d_in[1];   // (32, 4096, 1024)
    float* out = (float*)d_out;                 // [context (32*1024) | attn (32*4096)]
    float* ctx_out  = out;
    float* attn_out = out + (size_t)B_ * H_;

    cudaFuncSetAttribute(attn_fused, cudaFuncAttributeMaxDynamicSharedMemorySize,
                         SMEM_BYTES);

    dim3 grid(CHUNKS, B_);
    attn_fused<<<grid, 256, SMEM_BYTES>>>(dec, enc, ctx_out, attn_out);
}